// round 2
// baseline (speedup 1.0000x reference)
#include <cuda_runtime.h>
#include <cuda_bf16.h>
#include <cstdint>

// Problem constants (match reference_code)
#define N_NODES 50000
#define N_EDGES 800000
#define DIM     128

// -------- device scratch (no allocations allowed) --------
__device__ float g_agg[(size_t)N_NODES * DIM];
__device__ float g_h0 [(size_t)N_NODES * DIM];
__device__ float g_h1 [(size_t)N_NODES * DIM];
__device__ float g_deg[N_NODES];
__device__ float g_invdeg[N_NODES];

// -------- degree --------
__global__ void k_zero_deg() {
    int i = blockIdx.x * blockDim.x + threadIdx.x;
    if (i < N_NODES) g_deg[i] = 0.0f;
}
__global__ void k_count_deg(const int* __restrict__ dst) {
    int e = blockIdx.x * blockDim.x + threadIdx.x;
    if (e < N_EDGES) atomicAdd(&g_deg[dst[e]], 1.0f);
}
__global__ void k_invdeg() {
    int i = blockIdx.x * blockDim.x + threadIdx.x;
    if (i < N_NODES) g_invdeg[i] = 1.0f / fmaxf(g_deg[i], 1.0f);
}

// -------- zero agg (float4 stores) --------
__global__ void k_zero_agg() {
    size_t i = (size_t)blockIdx.x * blockDim.x + threadIdx.x;
    size_t n4 = (size_t)N_NODES * DIM / 4;
    if (i < n4) ((float4*)g_agg)[i] = make_float4(0.f, 0.f, 0.f, 0.f);
}

// -------- edge scatter: agg[dst] += h[src], vectorized red.global --------
// One warp per edge; each lane handles one float4 chunk (32 lanes * 4 = 128).
__global__ void k_scatter(const float* __restrict__ h,
                          const int* __restrict__ src,
                          const int* __restrict__ dst) {
    long long idx = (long long)blockIdx.x * blockDim.x + threadIdx.x;
    int e = (int)(idx >> 5);
    int c = (int)(idx & 31);
    if (e >= N_EDGES) return;
    int s = src[e];
    int d = dst[e];
    float4 v = ((const float4*)(h + (size_t)s * DIM))[c];
    float* p = g_agg + (size_t)d * DIM + (size_t)c * 4;
    asm volatile("red.global.add.v4.f32 [%0], {%1,%2,%3,%4};"
                 :: "l"(p), "f"(v.x), "f"(v.y), "f"(v.z), "f"(v.w)
                 : "memory");
}

// -------- fused GEMM: out = [h | agg*invdeg](M x 256) @ [Wself; Wneigh](256 x 128) + b, optional relu
template <bool RELU>
__global__ void k_gemm(const float* __restrict__ h,
                       const float* __restrict__ Wself,
                       const float* __restrict__ Wneigh,
                       const float* __restrict__ bias,
                       float* __restrict__ out) {
    constexpr int BM = 64, BN = 128, BK = 16, TM = 8, TN = 4;
    __shared__ float As[BK][BM];
    __shared__ float Bs[BK][BN];

    const int tid = threadIdx.x;           // 256 threads
    const int row0 = blockIdx.x * BM;
    const int tx = tid & 31;               // 32 col groups of TN=4
    const int ty = tid >> 5;               // 8 row groups of TM=8

    float acc[TM][TN];
#pragma unroll
    for (int i = 0; i < TM; i++)
#pragma unroll
        for (int j = 0; j < TN; j++) acc[i][j] = 0.f;

    // A-tile load mapping: 64 rows x 16 k, each thread one float4 along K
    const int arow = tid >> 2;             // 0..63
    const int ak   = (tid & 3) * 4;        // 0,4,8,12
    const int grow = row0 + arow;
    const bool rowok = (grow < N_NODES);
    const float idg = rowok ? g_invdeg[grow] : 0.f;

    // B-tile load mapping: 16 k-rows x 128 cols, each thread 2 float4
    const int brow = tid >> 4;             // 0..15
    const int bcol = (tid & 15) * 8;       // 0..120

    for (int k0 = 0; k0 < 2 * DIM; k0 += BK) {
        // ---- load A (virtual [h | agg*invdeg]) ----
        float4 av = make_float4(0.f, 0.f, 0.f, 0.f);
        if (rowok) {
            int kk = k0 + ak;
            if (kk < DIM) {
                av = *(const float4*)(h + (size_t)grow * DIM + kk);
            } else {
                av = *(const float4*)(g_agg + (size_t)grow * DIM + (kk - DIM));
                av.x *= idg; av.y *= idg; av.z *= idg; av.w *= idg;
            }
        }
        As[ak + 0][arow] = av.x;
        As[ak + 1][arow] = av.y;
        As[ak + 2][arow] = av.z;
        As[ak + 3][arow] = av.w;

        // ---- load B (stacked [Wself; Wneigh]) ----
        {
            int kk = k0 + brow;
            const float* Wp = (kk < DIM) ? (Wself + (size_t)kk * DIM)
                                         : (Wneigh + (size_t)(kk - DIM) * DIM);
            float4 b0 = *(const float4*)(Wp + bcol);
            float4 b1 = *(const float4*)(Wp + bcol + 4);
            *(float4*)&Bs[brow][bcol]     = b0;
            *(float4*)&Bs[brow][bcol + 4] = b1;
        }
        __syncthreads();

#pragma unroll
        for (int k = 0; k < BK; k++) {
            float a[TM];
#pragma unroll
            for (int i = 0; i < TM; i++) a[i] = As[k][ty * TM + i];
            float4 w4 = *(const float4*)&Bs[k][tx * TN];
            float w[TN] = {w4.x, w4.y, w4.z, w4.w};
#pragma unroll
            for (int i = 0; i < TM; i++)
#pragma unroll
                for (int j = 0; j < TN; j++) acc[i][j] += a[i] * w[j];
        }
        __syncthreads();
    }

    // ---- epilogue: bias (+relu), float4 stores ----
    const int c = tx * TN;
    float4 bb = *(const float4*)(bias + c);
#pragma unroll
    for (int i = 0; i < TM; i++) {
        int r = row0 + ty * TM + i;
        if (r < N_NODES) {
            float4 v;
            v.x = acc[i][0] + bb.x;
            v.y = acc[i][1] + bb.y;
            v.z = acc[i][2] + bb.z;
            v.w = acc[i][3] + bb.w;
            if (RELU) {
                v.x = fmaxf(v.x, 0.f); v.y = fmaxf(v.y, 0.f);
                v.z = fmaxf(v.z, 0.f); v.w = fmaxf(v.w, 0.f);
            }
            *(float4*)(out + (size_t)r * DIM + c) = v;
        }
    }
}

extern "C" void kernel_launch(void* const* d_in, const int* in_sizes, int n_in,
                              void* d_out, int out_size) {
    const float* x      = (const float*)d_in[0];
    const int*   src    = (const int*)d_in[1];
    const int*   dst    = (const int*)d_in[2];
    const float* W_self = (const float*)d_in[3];   // [3,128,128]
    const float* W_neigh= (const float*)d_in[4];   // [3,128,128]
    const float* b      = (const float*)d_in[5];   // [3,128]
    float* out = (float*)d_out;

    const int TPB = 256;
    const int nblk_nodes = (N_NODES + TPB - 1) / TPB;
    const int nblk_edges = (N_EDGES + TPB - 1) / TPB;
    const long long scat_threads = (long long)N_EDGES * 32;
    const int nblk_scat = (int)((scat_threads + TPB - 1) / TPB);
    const int nblk_zero = (int)(((size_t)N_NODES * DIM / 4 + TPB - 1) / TPB);
    const int nblk_gemm = (N_NODES + 63) / 64;

    // degrees (recomputed every call; deterministic)
    k_zero_deg<<<nblk_nodes, TPB>>>();
    k_count_deg<<<nblk_edges, TPB>>>(dst);
    k_invdeg<<<nblk_nodes, TPB>>>();

    const size_t WSZ = (size_t)DIM * DIM;

    // layer 0: x -> g_h0 (relu)
    k_zero_agg<<<nblk_zero, TPB>>>();
    k_scatter<<<nblk_scat, TPB>>>(x, src, dst);
    k_gemm<true><<<nblk_gemm, TPB>>>(x, W_self + 0 * WSZ, W_neigh + 0 * WSZ,
                                     b + 0 * DIM, g_h0);

    // layer 1: g_h0 -> g_h1 (relu)
    k_zero_agg<<<nblk_zero, TPB>>>();
    k_scatter<<<nblk_scat, TPB>>>(g_h0, src, dst);
    k_gemm<true><<<nblk_gemm, TPB>>>(g_h0, W_self + 1 * WSZ, W_neigh + 1 * WSZ,
                                     b + 1 * DIM, g_h1);

    // layer 2: g_h1 -> out (no relu)
    k_zero_agg<<<nblk_zero, TPB>>>();
    k_scatter<<<nblk_scat, TPB>>>(g_h1, src, dst);
    k_gemm<false><<<nblk_gemm, TPB>>>(g_h1, W_self + 2 * WSZ, W_neigh + 2 * WSZ,
                                      b + 2 * DIM, out);
}